// round 16
// baseline (speedup 1.0000x reference)
#include <cuda_runtime.h>
#include <cstdint>

// Problem constants (fixed shapes from reference)
#define BSZ 4
#define SEQ 1024
#define DIM 1024
#define NH 16
#define HD 64
#define MROWS (BSZ * SEQ)   // 4096

// Scratch (allocation-free rule: __device__ globals)
// q is pre-scaled by 0.125*log2(e) and tf32-rounded; k,v tf32-rounded.
__device__ float g_q[(size_t)BSZ * NH * SEQ * HD];
__device__ float g_k[(size_t)BSZ * NH * SEQ * HD];
__device__ float g_v[(size_t)BSZ * NH * SEQ * HD];
__device__ float g_attn[(size_t)MROWS * DIM];         // merged-head [B*S, D]

__device__ __forceinline__ unsigned f2tf32(float f) {
    unsigned u;
    asm("cvt.rna.tf32.f32 %0, %1;" : "=r"(u) : "f"(f));
    return u;
}
__device__ __forceinline__ float tf32r(float x) { return __uint_as_float(f2tf32(x)); }

__device__ __forceinline__ void mma1688(float c[4], const unsigned a[4],
                                        unsigned b0, unsigned b1) {
    asm volatile(
        "mma.sync.aligned.m16n8k8.row.col.f32.tf32.tf32.f32 "
        "{%0,%1,%2,%3}, {%4,%5,%6,%7}, {%8,%9}, {%0,%1,%2,%3};"
        : "+f"(c[0]), "+f"(c[1]), "+f"(c[2]), "+f"(c[3])
        : "r"(a[0]), "r"(a[1]), "r"(a[2]), "r"(a[3]), "r"(b0), "r"(b1));
}

__device__ __forceinline__ void cpa16(uint32_t s, const float* gp) {
    asm volatile("cp.async.cg.shared.global [%0], [%1], 16;" :: "r"(s), "l"(gp));
}

// Branch-free exp2 on the FFMA pipe (no MUFU). Input must be <= 0; values
// below -30 clamp to 2^-30 (mask semantics: weight ~1e-9 ~ ref's e^-10000).
__device__ __forceinline__ float exp2fast(float y) {
    y = fmaxf(y, -30.0f);
    float tt = y + 12582912.0f;            // round-to-nearest integer split
    float f  = y - (tt - 12582912.0f);     // f in [-0.5, 0.5]
    int   ib = __float_as_int(tt);
    // deg-5 Taylor of 2^f on [-0.5,0.5], rel err ~2.4e-6
    float p = 0.0013333558f;
    p = fmaf(p, f, 0.0096181291f);
    p = fmaf(p, f, 0.0555041087f);
    p = fmaf(p, f, 0.2402265069f);
    p = fmaf(p, f, 0.6931471806f);
    p = fmaf(p, f, 1.0f);
    float s = __int_as_float((ib + (127 - 0x4B400000)) << 23);  // 2^round(y)
    return p * s;
}

// ---------------------------------------------------------------------------
// TF32 tensor-core GEMM: C[M,N] = A[M,K] @ B[K,N] + bias[N]
// BM=BN=128, BK=16, 256 threads (8 warps), warp tile 64x32 via m16n8k8 mma.
// MODE 0: scatter into g_q/g_k/g_v (head-major), q scaled by 0.125*log2e,
//         all three tf32-rounded (so flash needs no per-fragment converts)
// MODE 1: A = g_attn, plain store to C (= d_out)
// ---------------------------------------------------------------------------
#define AS_STRIDE 20
#define BS_STRIDE 136
#define QSCALE 0.1803368801111245f   // 0.125 * log2(e)

template <int MODE>
__global__ __launch_bounds__(256) void mma_gemm_kernel(
    const float* __restrict__ A_in, const float* __restrict__ Bm,
    const float* __restrict__ bias, float* __restrict__ C,
    int N, int K)
{
    const float* A = (MODE == 0) ? A_in : (const float*)g_attn;

    __shared__ unsigned As[2][128 * AS_STRIDE];   // [m][k], tf32 bits
    __shared__ unsigned Bs[2][16 * BS_STRIDE];    // [k][n], tf32 bits

    const int tid  = threadIdx.x;
    const int lane = tid & 31;
    const int w    = tid >> 5;
    const int wm   = w & 1;
    const int wn   = w >> 1;
    const int m0   = blockIdx.y * 128;
    const int n0   = blockIdx.x * 128;

    float acc[4][4][4];
#pragma unroll
    for (int mt = 0; mt < 4; mt++)
#pragma unroll
        for (int nt = 0; nt < 4; nt++)
#pragma unroll
            for (int e = 0; e < 4; e++) acc[mt][nt][e] = 0.f;

    float4 pa[2], pb[2];

#define LOAD_G(k0)                                                          \
    {                                                                       \
        _Pragma("unroll")                                                   \
        for (int it = 0; it < 2; it++) {                                    \
            int i = tid + it * 256;                                         \
            pa[it] = *reinterpret_cast<const float4*>(                      \
                &A[(size_t)(m0 + (i >> 2)) * K + (k0) + ((i & 3) << 2)]);   \
            pb[it] = *reinterpret_cast<const float4*>(                      \
                &Bm[(size_t)((k0) + (i >> 5)) * N + n0 + ((i & 31) << 2)]); \
        }                                                                   \
    }

#define STORE_S(buf)                                                        \
    {                                                                       \
        _Pragma("unroll")                                                   \
        for (int it = 0; it < 2; it++) {                                    \
            int i = tid + it * 256;                                         \
            unsigned* pA = &As[buf][(i >> 2) * AS_STRIDE + ((i & 3) << 2)]; \
            pA[0] = f2tf32(pa[it].x); pA[1] = f2tf32(pa[it].y);             \
            pA[2] = f2tf32(pa[it].z); pA[3] = f2tf32(pa[it].w);             \
            unsigned* pB = &Bs[buf][(i >> 5) * BS_STRIDE + ((i & 31) << 2)];\
            pB[0] = f2tf32(pb[it].x); pB[1] = f2tf32(pb[it].y);             \
            pB[2] = f2tf32(pb[it].z); pB[3] = f2tf32(pb[it].w);             \
        }                                                                   \
    }

    LOAD_G(0);
    STORE_S(0);
    __syncthreads();

    const int niter = K / 16;
    for (int kt = 0; kt < niter; kt++) {
        const int buf = kt & 1;
        if (kt + 1 < niter) LOAD_G((kt + 1) * 16);

#pragma unroll
        for (int ks = 0; ks < 16; ks += 8) {
            unsigned af[4][4], bf[4][2];
#pragma unroll
            for (int mt = 0; mt < 4; mt++) {
                int row = wm * 64 + mt * 16 + (lane >> 2);
                const unsigned* base = &As[buf][row * AS_STRIDE + ks + (lane & 3)];
                af[mt][0] = base[0];
                af[mt][1] = base[8 * AS_STRIDE];
                af[mt][2] = base[4];
                af[mt][3] = base[8 * AS_STRIDE + 4];
            }
#pragma unroll
            for (int nt = 0; nt < 4; nt++) {
                int col = wn * 32 + nt * 8 + (lane >> 2);
                const unsigned* base = &Bs[buf][(ks + (lane & 3)) * BS_STRIDE + col];
                bf[nt][0] = base[0];
                bf[nt][1] = base[4 * BS_STRIDE];
            }
#pragma unroll
            for (int mt = 0; mt < 4; mt++)
#pragma unroll
                for (int nt = 0; nt < 4; nt++)
                    mma1688(acc[mt][nt], af[mt], bf[nt][0], bf[nt][1]);
        }

        if (kt + 1 < niter) STORE_S(buf ^ 1);
        __syncthreads();
    }

#pragma unroll
    for (int mt = 0; mt < 4; mt++) {
#pragma unroll
        for (int nt = 0; nt < 4; nt++) {
#pragma unroll
            for (int e = 0; e < 4; e++) {
                int m = m0 + wm * 64 + mt * 16 + (lane >> 2) + ((e >> 1) ? 8 : 0);
                int n = n0 + wn * 32 + nt * 8 + (lane & 3) * 2 + (e & 1);
                float val = acc[mt][nt][e] + __ldg(&bias[n]);
                if (MODE == 0) {
                    int bb = m >> 10;
                    int s  = m & 1023;
                    int part = n >> 10;          // 0=q, 1=k, 2=v
                    int d = n & 1023;
                    int h = d >> 6;
                    int el = d & 63;
                    size_t idx = ((size_t)(bb * NH + h) * SEQ + s) * HD + el;
                    if (part == 0)      g_q[idx] = tf32r(val * QSCALE);
                    else if (part == 1) g_k[idx] = tf32r(val);
                    else                g_v[idx] = tf32r(val);
                } else {
                    C[(size_t)m * N + n] = val;
                }
            }
        }
    }
}

// ---------------------------------------------------------------------------
// Tensor-core causal flash attention (tf32 mma, exp2 in FFMA, cp.async KV).
// CTA: 256 threads (8 warps), 128 q-rows; warp w owns rows 16w..16w+15.
// Key tiles of 64, K/V double-buffered. P routed via per-warp smem to convert
// C-fragment layout -> A-fragment layout for the PV mma.
// Grid: (S/128 [reversed: heavy tiles first], B*H)
// ---------------------------------------------------------------------------
#define SK_STRIDE 68   // banks: 4g+t  (conflict-free K & P fragment reads)
#define SV_STRIDE 72   // banks: 8a+b  (conflict-free V fragment reads)
#define SP_STRIDE 68
#define FLASH_SMEM ((2*64*SK_STRIDE + 2*64*SV_STRIDE + 8*16*SP_STRIDE) * 4)

__global__ __launch_bounds__(256) void flash2_kernel()
{
    extern __shared__ float dsm[];
    float* sK = dsm;                               // [2][64*SK_STRIDE]
    float* sV = dsm + 2 * 64 * SK_STRIDE;          // [2][64*SV_STRIDE]
    float* sPall = sV + 2 * 64 * SV_STRIDE;        // [8][16*SP_STRIDE]

    const int bh    = blockIdx.y;
    const int qt    = gridDim.x - 1 - blockIdx.x;  // heavy q-tiles first
    const int qbase = qt * 128;
    const int tid   = threadIdx.x;
    const int lane  = tid & 31;
    const int w     = tid >> 5;
    const int g     = lane >> 2;      // fragment group row
    const int t4    = lane & 3;       // fragment thread-in-group

    float* sP = sPall + w * 16 * SP_STRIDE;
    const unsigned* uP = reinterpret_cast<const unsigned*>(sP);

    const float* Kg = g_k + (size_t)bh * SEQ * HD;
    const float* Vg = g_v + (size_t)bh * SEQ * HD;

    // Q fragments for this warp's 16 rows (values already tf32+log2e-scaled)
    const int qr0 = qbase + 16 * w + g;
    const float* Qp0 = g_q + ((size_t)bh * SEQ + qr0) * HD;
    const float* Qp8 = Qp0 + 8 * HD;
    unsigned af[8][4];
#pragma unroll
    for (int kc = 0; kc < 8; kc++) {
        af[kc][0] = __float_as_uint(__ldg(&Qp0[kc * 8 + t4]));
        af[kc][1] = __float_as_uint(__ldg(&Qp8[kc * 8 + t4]));
        af[kc][2] = __float_as_uint(__ldg(&Qp0[kc * 8 + t4 + 4]));
        af[kc][3] = __float_as_uint(__ldg(&Qp8[kc * 8 + t4 + 4]));
    }

    float oc[8][4];
#pragma unroll
    for (int dn = 0; dn < 8; dn++)
#pragma unroll
        for (int e = 0; e < 4; e++) oc[dn][e] = 0.f;
    float m0 = -100000.f, m8 = -100000.f, l0 = 0.f, l8 = 0.f;

    const int ntiles = 2 * qt + 2;
    const uint32_t sKa = (uint32_t)__cvta_generic_to_shared(sK);
    const uint32_t sVa = (uint32_t)__cvta_generic_to_shared(sV);

#define LOAD_KV(tile, buf)                                                   \
    {                                                                        \
        int _j0 = (tile) * 64;                                               \
        _Pragma("unroll")                                                    \
        for (int it = 0; it < 4; it++) {                                     \
            int i = tid + it * 256;                                          \
            int key = i >> 4;                                                \
            int d4 = (i & 15) << 2;                                          \
            cpa16(sKa + (((buf) * 64 + key) * SK_STRIDE + d4) * 4,           \
                  Kg + (size_t)(_j0 + key) * HD + d4);                       \
            cpa16(sVa + (((buf) * 64 + key) * SV_STRIDE + d4) * 4,           \
                  Vg + (size_t)(_j0 + key) * HD + d4);                       \
        }                                                                    \
        asm volatile("cp.async.commit_group;" ::: "memory");                 \
    }

    LOAD_KV(0, 0);

    for (int tile = 0; tile < ntiles; tile++) {
        if (tile + 1 < ntiles) {
            LOAD_KV(tile + 1, (tile + 1) & 1);
            asm volatile("cp.async.wait_group 1;" ::: "memory");
        } else {
            asm volatile("cp.async.wait_group 0;" ::: "memory");
        }
        __syncthreads();

        const int j0 = tile * 64;
        const bool skip = (j0 > qbase + 16 * w + 15);   // warp fully masked
        if (!skip) {
            const unsigned* uK = reinterpret_cast<const unsigned*>(
                sK + (tile & 1) * 64 * SK_STRIDE);
            const unsigned* uV = reinterpret_cast<const unsigned*>(
                sV + (tile & 1) * 64 * SV_STRIDE);

            // ---- S = Q K^T (scores already in log2 units) ----
            float sc[8][4];
#pragma unroll
            for (int nt = 0; nt < 8; nt++)
#pragma unroll
                for (int e = 0; e < 4; e++) sc[nt][e] = 0.f;

#pragma unroll
            for (int kc = 0; kc < 8; kc++) {
#pragma unroll
                for (int nt = 0; nt < 8; nt++) {
                    unsigned b0 = uK[(nt * 8 + g) * SK_STRIDE + kc * 8 + t4];
                    unsigned b1 = uK[(nt * 8 + g) * SK_STRIDE + kc * 8 + t4 + 4];
                    mma1688(sc[nt], af[kc], b0, b1);
                }
            }

            // ---- causal mask ----
            if (j0 + 63 > qbase + 16 * w) {
#pragma unroll
                for (int nt = 0; nt < 8; nt++) {
                    int key0 = j0 + nt * 8 + 2 * t4;
                    if (key0     > qr0)     sc[nt][0] = -100000.f;
                    if (key0 + 1 > qr0)     sc[nt][1] = -100000.f;
                    if (key0     > qr0 + 8) sc[nt][2] = -100000.f;
                    if (key0 + 1 > qr0 + 8) sc[nt][3] = -100000.f;
                }
            }

            // ---- online softmax (base-2) ----
            float mx0 = fmaxf(sc[0][0], sc[0][1]);
            float mx8 = fmaxf(sc[0][2], sc[0][3]);
#pragma unroll
            for (int nt = 1; nt < 8; nt++) {
                mx0 = fmaxf(mx0, fmaxf(sc[nt][0], sc[nt][1]));
                mx8 = fmaxf(mx8, fmaxf(sc[nt][2], sc[nt][3]));
            }
            mx0 = fmaxf(mx0, __shfl_xor_sync(0xffffffffu, mx0, 1));
            mx0 = fmaxf(mx0, __shfl_xor_sync(0xffffffffu, mx0, 2));
            mx8 = fmaxf(mx8, __shfl_xor_sync(0xffffffffu, mx8, 1));
            mx8 = fmaxf(mx8, __shfl_xor_sync(0xffffffffu, mx8, 2));

            float mn0 = fmaxf(m0, mx0), mn8 = fmaxf(m8, mx8);
            float c0 = exp2fast(m0 - mn0), c8 = exp2fast(m8 - mn8);
            m0 = mn0; m8 = mn8;

            float s0 = 0.f, s8 = 0.f;
#pragma unroll
            for (int nt = 0; nt < 8; nt++) {
                float p0 = exp2fast(sc[nt][0] - mn0);
                float p1 = exp2fast(sc[nt][1] - mn0);
                float p2 = exp2fast(sc[nt][2] - mn8);
                float p3 = exp2fast(sc[nt][3] - mn8);
                s0 += p0 + p1;
                s8 += p2 + p3;
                *reinterpret_cast<float2*>(&sP[g * SP_STRIDE + nt * 8 + 2 * t4]) =
                    make_float2(__uint_as_float(f2tf32(p0)), __uint_as_float(f2tf32(p1)));
                *reinterpret_cast<float2*>(&sP[(g + 8) * SP_STRIDE + nt * 8 + 2 * t4]) =
                    make_float2(__uint_as_float(f2tf32(p2)), __uint_as_float(f2tf32(p3)));
            }
            s0 += __shfl_xor_sync(0xffffffffu, s0, 1);
            s0 += __shfl_xor_sync(0xffffffffu, s0, 2);
            s8 += __shfl_xor_sync(0xffffffffu, s8, 1);
            s8 += __shfl_xor_sync(0xffffffffu, s8, 2);
            l0 = l0 * c0 + s0;
            l8 = l8 * c8 + s8;
#pragma unroll
            for (int dn = 0; dn < 8; dn++) {
                oc[dn][0] *= c0; oc[dn][1] *= c0;
                oc[dn][2] *= c8; oc[dn][3] *= c8;
            }

            __syncwarp();

            // ---- O += P V ----
#pragma unroll
            for (int kc = 0; kc < 8; kc++) {
                unsigned ap[4];
                ap[0] = uP[g * SP_STRIDE + kc * 8 + t4];
                ap[1] = uP[(g + 8) * SP_STRIDE + kc * 8 + t4];
                ap[2] = uP[g * SP_STRIDE + kc * 8 + t4 + 4];
                ap[3] = uP[(g + 8) * SP_STRIDE + kc * 8 + t4 + 4];
#pragma unroll
                for (int dn = 0; dn < 8; dn++) {
                    unsigned b0 = uV[(kc * 8 + t4) * SV_STRIDE + dn * 8 + g];
                    unsigned b1 = uV[(kc * 8 + t4 + 4) * SV_STRIDE + dn * 8 + g];
                    mma1688(oc[dn], ap, b0, b1);
                }
            }
        }
        __syncthreads();
    }

    // ---- epilogue: O / l, merge heads into g_attn [B*S, D] ----
    const float inv0 = 1.f / l0, inv8 = 1.f / l8;
    const int bb = bh >> 4;
    const int h = bh & 15;
    float* D0 = g_attn + ((size_t)(bb * SEQ) + qr0) * DIM + h * HD;
    float* D8 = D0 + 8 * DIM;
#pragma unroll
    for (int dn = 0; dn < 8; dn++) {
        int d = dn * 8 + 2 * t4;
        *reinterpret_cast<float2*>(&D0[d]) =
            make_float2(oc[dn][0] * inv0, oc[dn][1] * inv0);
        *reinterpret_cast<float2*>(&D8[d]) =
            make_float2(oc[dn][2] * inv8, oc[dn][3] * inv8);
    }
}

// ---------------------------------------------------------------------------
extern "C" void kernel_launch(void* const* d_in, const int* in_sizes, int n_in,
                              void* d_out, int out_size)
{
    const float* x      = (const float*)d_in[0];   // [4,1024,1024]
    const float* w_attn = (const float*)d_in[1];   // [1024,3072]
    const float* b_attn = (const float*)d_in[2];   // [3072]
    const float* w_proj = (const float*)d_in[3];   // [1024,1024]
    const float* b_proj = (const float*)d_in[4];   // [1024]
    float* out = (float*)d_out;                    // [4,1024,1024]

    cudaFuncSetAttribute(flash2_kernel,
                         cudaFuncAttributeMaxDynamicSharedMemorySize, FLASH_SMEM);

    // 1) QKV GEMM (TF32) + head-major scatter, q pre-scaled by 0.125*log2e,
    //    q/k/v tf32-rounded for the flash mma stage
    mma_gemm_kernel<0><<<dim3(3 * DIM / 128, MROWS / 128), 256>>>(
        x, w_attn, b_attn, nullptr, 3 * DIM, DIM);

    // 2) tensor-core causal flash attention (writes merged-head g_attn)
    flash2_kernel<<<dim3(SEQ / 128, BSZ * NH), 256, FLASH_SMEM>>>();

    // 3) output projection (TF32 tensor cores)
    mma_gemm_kernel<1><<<dim3(DIM / 128, MROWS / 128), 256>>>(
        nullptr, w_proj, b_proj, out, DIM, DIM);
}

// round 17
// speedup vs baseline: 1.0054x; 1.0054x over previous
#include <cuda_runtime.h>
#include <cstdint>

// Problem constants (fixed shapes from reference)
#define BSZ 4
#define SEQ 1024
#define DIM 1024
#define NH 16
#define HD 64
#define MROWS (BSZ * SEQ)   // 4096

// Scratch (allocation-free rule: __device__ globals)
// q is pre-scaled by 0.125*log2(e) and tf32-rounded; k,v tf32-rounded.
__device__ float g_q[(size_t)BSZ * NH * SEQ * HD];
__device__ float g_k[(size_t)BSZ * NH * SEQ * HD];
__device__ float g_v[(size_t)BSZ * NH * SEQ * HD];
__device__ float g_attn[(size_t)MROWS * DIM];         // merged-head [B*S, D]

__device__ __forceinline__ unsigned f2tf32(float f) {
    unsigned u;
    asm("cvt.rna.tf32.f32 %0, %1;" : "=r"(u) : "f"(f));
    return u;
}
__device__ __forceinline__ float tf32r(float x) { return __uint_as_float(f2tf32(x)); }

__device__ __forceinline__ void mma1688(float c[4], const unsigned a[4],
                                        unsigned b0, unsigned b1) {
    asm volatile(
        "mma.sync.aligned.m16n8k8.row.col.f32.tf32.tf32.f32 "
        "{%0,%1,%2,%3}, {%4,%5,%6,%7}, {%8,%9}, {%0,%1,%2,%3};"
        : "+f"(c[0]), "+f"(c[1]), "+f"(c[2]), "+f"(c[3])
        : "r"(a[0]), "r"(a[1]), "r"(a[2]), "r"(a[3]), "r"(b0), "r"(b1));
}

__device__ __forceinline__ void cpa16(uint32_t s, const float* gp) {
    asm volatile("cp.async.cg.shared.global [%0], [%1], 16;" :: "r"(s), "l"(gp));
}

// Branch-free exp2 on the FFMA pipe (no MUFU). Input must be <= 0; values
// below -30 clamp to 2^-30 (mask semantics: weight ~1e-9 ~ ref's e^-10000).
__device__ __forceinline__ float exp2fast(float y) {
    y = fmaxf(y, -30.0f);
    float tt = y + 12582912.0f;            // round-to-nearest integer split
    float f  = y - (tt - 12582912.0f);     // f in [-0.5, 0.5]
    int   ib = __float_as_int(tt);
    // deg-5 Taylor of 2^f on [-0.5,0.5], rel err ~2.4e-6
    float p = 0.0013333558f;
    p = fmaf(p, f, 0.0096181291f);
    p = fmaf(p, f, 0.0555041087f);
    p = fmaf(p, f, 0.2402265069f);
    p = fmaf(p, f, 0.6931471806f);
    p = fmaf(p, f, 1.0f);
    float s = __int_as_float((ib + (127 - 0x4B400000)) << 23);  // 2^round(y)
    return p * s;
}

// ---------------------------------------------------------------------------
// TF32 tensor-core GEMM: C[M,N] = A[M,K] @ B[K,N] + bias[N]
// BM=BN=128, BK=16, 256 threads (8 warps), warp tile 64x32 via m16n8k8 mma.
// MODE 0: scatter into g_q/g_k/g_v (head-major), q scaled by 0.125*log2e,
//         all three tf32-rounded (so flash needs no per-fragment converts)
// MODE 1: A = g_attn, plain store to C (= d_out)
// ---------------------------------------------------------------------------
#define AS_STRIDE 20
#define BS_STRIDE 136
#define QSCALE 0.1803368801111245f   // 0.125 * log2(e)

template <int MODE>
__global__ __launch_bounds__(256) void mma_gemm_kernel(
    const float* __restrict__ A_in, const float* __restrict__ Bm,
    const float* __restrict__ bias, float* __restrict__ C,
    int N, int K)
{
    const float* A = (MODE == 0) ? A_in : (const float*)g_attn;

    __shared__ unsigned As[2][128 * AS_STRIDE];   // [m][k], tf32 bits
    __shared__ unsigned Bs[2][16 * BS_STRIDE];    // [k][n], tf32 bits

    const int tid  = threadIdx.x;
    const int lane = tid & 31;
    const int w    = tid >> 5;
    const int wm   = w & 1;
    const int wn   = w >> 1;
    const int m0   = blockIdx.y * 128;
    const int n0   = blockIdx.x * 128;

    float acc[4][4][4];
#pragma unroll
    for (int mt = 0; mt < 4; mt++)
#pragma unroll
        for (int nt = 0; nt < 4; nt++)
#pragma unroll
            for (int e = 0; e < 4; e++) acc[mt][nt][e] = 0.f;

    float4 pa[2], pb[2];

#define LOAD_G(k0)                                                          \
    {                                                                       \
        _Pragma("unroll")                                                   \
        for (int it = 0; it < 2; it++) {                                    \
            int i = tid + it * 256;                                         \
            pa[it] = *reinterpret_cast<const float4*>(                      \
                &A[(size_t)(m0 + (i >> 2)) * K + (k0) + ((i & 3) << 2)]);   \
            pb[it] = *reinterpret_cast<const float4*>(                      \
                &Bm[(size_t)((k0) + (i >> 5)) * N + n0 + ((i & 31) << 2)]); \
        }                                                                   \
    }

#define STORE_S(buf)                                                        \
    {                                                                       \
        _Pragma("unroll")                                                   \
        for (int it = 0; it < 2; it++) {                                    \
            int i = tid + it * 256;                                         \
            unsigned* pA = &As[buf][(i >> 2) * AS_STRIDE + ((i & 3) << 2)]; \
            pA[0] = f2tf32(pa[it].x); pA[1] = f2tf32(pa[it].y);             \
            pA[2] = f2tf32(pa[it].z); pA[3] = f2tf32(pa[it].w);             \
            unsigned* pB = &Bs[buf][(i >> 5) * BS_STRIDE + ((i & 31) << 2)];\
            pB[0] = f2tf32(pb[it].x); pB[1] = f2tf32(pb[it].y);             \
            pB[2] = f2tf32(pb[it].z); pB[3] = f2tf32(pb[it].w);             \
        }                                                                   \
    }

    LOAD_G(0);
    STORE_S(0);
    __syncthreads();

    const int niter = K / 16;
    for (int kt = 0; kt < niter; kt++) {
        const int buf = kt & 1;
        if (kt + 1 < niter) LOAD_G((kt + 1) * 16);

#pragma unroll
        for (int ks = 0; ks < 16; ks += 8) {
            unsigned af[4][4], bf[4][2];
#pragma unroll
            for (int mt = 0; mt < 4; mt++) {
                int row = wm * 64 + mt * 16 + (lane >> 2);
                const unsigned* base = &As[buf][row * AS_STRIDE + ks + (lane & 3)];
                af[mt][0] = base[0];
                af[mt][1] = base[8 * AS_STRIDE];
                af[mt][2] = base[4];
                af[mt][3] = base[8 * AS_STRIDE + 4];
            }
#pragma unroll
            for (int nt = 0; nt < 4; nt++) {
                int col = wn * 32 + nt * 8 + (lane >> 2);
                const unsigned* base = &Bs[buf][(ks + (lane & 3)) * BS_STRIDE + col];
                bf[nt][0] = base[0];
                bf[nt][1] = base[4 * BS_STRIDE];
            }
#pragma unroll
            for (int mt = 0; mt < 4; mt++)
#pragma unroll
                for (int nt = 0; nt < 4; nt++)
                    mma1688(acc[mt][nt], af[mt], bf[nt][0], bf[nt][1]);
        }

        if (kt + 1 < niter) STORE_S(buf ^ 1);
        __syncthreads();
    }

#pragma unroll
    for (int mt = 0; mt < 4; mt++) {
#pragma unroll
        for (int nt = 0; nt < 4; nt++) {
#pragma unroll
            for (int e = 0; e < 4; e++) {
                int m = m0 + wm * 64 + mt * 16 + (lane >> 2) + ((e >> 1) ? 8 : 0);
                int n = n0 + wn * 32 + nt * 8 + (lane & 3) * 2 + (e & 1);
                float val = acc[mt][nt][e] + __ldg(&bias[n]);
                if (MODE == 0) {
                    int bb = m >> 10;
                    int s  = m & 1023;
                    int part = n >> 10;          // 0=q, 1=k, 2=v
                    int d = n & 1023;
                    int h = d >> 6;
                    int el = d & 63;
                    size_t idx = ((size_t)(bb * NH + h) * SEQ + s) * HD + el;
                    if (part == 0)      g_q[idx] = tf32r(val * QSCALE);
                    else if (part == 1) g_k[idx] = tf32r(val);
                    else                g_v[idx] = tf32r(val);
                } else {
                    C[(size_t)m * N + n] = val;
                }
            }
        }
    }
}

// ---------------------------------------------------------------------------
// Tensor-core causal flash attention (tf32 mma, exp2 in FFMA, cp.async KV).
// CTA: 256 threads (8 warps), 128 q-rows; warp w owns rows 16w..16w+15.
// Key tiles of 64, K/V double-buffered. P routed via per-warp smem to convert
// C-fragment layout -> A-fragment layout for the PV mma.
// Grid: (S/128 [reversed: heavy tiles first], B*H)
// ---------------------------------------------------------------------------
#define SK_STRIDE 68   // banks: 4g+t  (conflict-free K & P fragment reads)
#define SV_STRIDE 72   // banks: 8a+b  (conflict-free V fragment reads)
#define SP_STRIDE 68
#define FLASH_SMEM ((2*64*SK_STRIDE + 2*64*SV_STRIDE + 8*16*SP_STRIDE) * 4)

__global__ __launch_bounds__(256) void flash2_kernel()
{
    extern __shared__ float dsm[];
    float* sK = dsm;                               // [2][64*SK_STRIDE]
    float* sV = dsm + 2 * 64 * SK_STRIDE;          // [2][64*SV_STRIDE]
    float* sPall = sV + 2 * 64 * SV_STRIDE;        // [8][16*SP_STRIDE]

    const int bh    = blockIdx.y;
    const int qt    = gridDim.x - 1 - blockIdx.x;  // heavy q-tiles first
    const int qbase = qt * 128;
    const int tid   = threadIdx.x;
    const int lane  = tid & 31;
    const int w     = tid >> 5;
    const int g     = lane >> 2;      // fragment group row
    const int t4    = lane & 3;       // fragment thread-in-group

    float* sP = sPall + w * 16 * SP_STRIDE;
    const unsigned* uP = reinterpret_cast<const unsigned*>(sP);

    const float* Kg = g_k + (size_t)bh * SEQ * HD;
    const float* Vg = g_v + (size_t)bh * SEQ * HD;

    // Q fragments for this warp's 16 rows (values already tf32+log2e-scaled)
    const int qr0 = qbase + 16 * w + g;
    const float* Qp0 = g_q + ((size_t)bh * SEQ + qr0) * HD;
    const float* Qp8 = Qp0 + 8 * HD;
    unsigned af[8][4];
#pragma unroll
    for (int kc = 0; kc < 8; kc++) {
        af[kc][0] = __float_as_uint(__ldg(&Qp0[kc * 8 + t4]));
        af[kc][1] = __float_as_uint(__ldg(&Qp8[kc * 8 + t4]));
        af[kc][2] = __float_as_uint(__ldg(&Qp0[kc * 8 + t4 + 4]));
        af[kc][3] = __float_as_uint(__ldg(&Qp8[kc * 8 + t4 + 4]));
    }

    float oc[8][4];
#pragma unroll
    for (int dn = 0; dn < 8; dn++)
#pragma unroll
        for (int e = 0; e < 4; e++) oc[dn][e] = 0.f;
    float m0 = -100000.f, m8 = -100000.f, l0 = 0.f, l8 = 0.f;

    const int ntiles = 2 * qt + 2;
    const uint32_t sKa = (uint32_t)__cvta_generic_to_shared(sK);
    const uint32_t sVa = (uint32_t)__cvta_generic_to_shared(sV);

#define LOAD_KV(tile, buf)                                                   \
    {                                                                        \
        int _j0 = (tile) * 64;                                               \
        _Pragma("unroll")                                                    \
        for (int it = 0; it < 4; it++) {                                     \
            int i = tid + it * 256;                                          \
            int key = i >> 4;                                                \
            int d4 = (i & 15) << 2;                                          \
            cpa16(sKa + (((buf) * 64 + key) * SK_STRIDE + d4) * 4,           \
                  Kg + (size_t)(_j0 + key) * HD + d4);                       \
            cpa16(sVa + (((buf) * 64 + key) * SV_STRIDE + d4) * 4,           \
                  Vg + (size_t)(_j0 + key) * HD + d4);                       \
        }                                                                    \
        asm volatile("cp.async.commit_group;" ::: "memory");                 \
    }

    LOAD_KV(0, 0);

    for (int tile = 0; tile < ntiles; tile++) {
        if (tile + 1 < ntiles) {
            LOAD_KV(tile + 1, (tile + 1) & 1);
            asm volatile("cp.async.wait_group 1;" ::: "memory");
        } else {
            asm volatile("cp.async.wait_group 0;" ::: "memory");
        }
        __syncthreads();

        const int j0 = tile * 64;
        const bool skip = (j0 > qbase + 16 * w + 15);   // warp fully masked
        if (!skip) {
            const unsigned* uK = reinterpret_cast<const unsigned*>(
                sK + (tile & 1) * 64 * SK_STRIDE);
            const unsigned* uV = reinterpret_cast<const unsigned*>(
                sV + (tile & 1) * 64 * SV_STRIDE);

            // ---- S = Q K^T (scores already in log2 units) ----
            float sc[8][4];
#pragma unroll
            for (int nt = 0; nt < 8; nt++)
#pragma unroll
                for (int e = 0; e < 4; e++) sc[nt][e] = 0.f;

#pragma unroll
            for (int kc = 0; kc < 8; kc++) {
#pragma unroll
                for (int nt = 0; nt < 8; nt++) {
                    unsigned b0 = uK[(nt * 8 + g) * SK_STRIDE + kc * 8 + t4];
                    unsigned b1 = uK[(nt * 8 + g) * SK_STRIDE + kc * 8 + t4 + 4];
                    mma1688(sc[nt], af[kc], b0, b1);
                }
            }

            // ---- causal mask ----
            if (j0 + 63 > qbase + 16 * w) {
#pragma unroll
                for (int nt = 0; nt < 8; nt++) {
                    int key0 = j0 + nt * 8 + 2 * t4;
                    if (key0     > qr0)     sc[nt][0] = -100000.f;
                    if (key0 + 1 > qr0)     sc[nt][1] = -100000.f;
                    if (key0     > qr0 + 8) sc[nt][2] = -100000.f;
                    if (key0 + 1 > qr0 + 8) sc[nt][3] = -100000.f;
                }
            }

            // ---- online softmax (base-2) ----
            float mx0 = fmaxf(sc[0][0], sc[0][1]);
            float mx8 = fmaxf(sc[0][2], sc[0][3]);
#pragma unroll
            for (int nt = 1; nt < 8; nt++) {
                mx0 = fmaxf(mx0, fmaxf(sc[nt][0], sc[nt][1]));
                mx8 = fmaxf(mx8, fmaxf(sc[nt][2], sc[nt][3]));
            }
            mx0 = fmaxf(mx0, __shfl_xor_sync(0xffffffffu, mx0, 1));
            mx0 = fmaxf(mx0, __shfl_xor_sync(0xffffffffu, mx0, 2));
            mx8 = fmaxf(mx8, __shfl_xor_sync(0xffffffffu, mx8, 1));
            mx8 = fmaxf(mx8, __shfl_xor_sync(0xffffffffu, mx8, 2));

            float mn0 = fmaxf(m0, mx0), mn8 = fmaxf(m8, mx8);
            float c0 = exp2fast(m0 - mn0), c8 = exp2fast(m8 - mn8);
            m0 = mn0; m8 = mn8;

            float s0 = 0.f, s8 = 0.f;
#pragma unroll
            for (int nt = 0; nt < 8; nt++) {
                float p0 = exp2fast(sc[nt][0] - mn0);
                float p1 = exp2fast(sc[nt][1] - mn0);
                float p2 = exp2fast(sc[nt][2] - mn8);
                float p3 = exp2fast(sc[nt][3] - mn8);
                s0 += p0 + p1;
                s8 += p2 + p3;
                *reinterpret_cast<float2*>(&sP[g * SP_STRIDE + nt * 8 + 2 * t4]) =
                    make_float2(__uint_as_float(f2tf32(p0)), __uint_as_float(f2tf32(p1)));
                *reinterpret_cast<float2*>(&sP[(g + 8) * SP_STRIDE + nt * 8 + 2 * t4]) =
                    make_float2(__uint_as_float(f2tf32(p2)), __uint_as_float(f2tf32(p3)));
            }
            s0 += __shfl_xor_sync(0xffffffffu, s0, 1);
            s0 += __shfl_xor_sync(0xffffffffu, s0, 2);
            s8 += __shfl_xor_sync(0xffffffffu, s8, 1);
            s8 += __shfl_xor_sync(0xffffffffu, s8, 2);
            l0 = l0 * c0 + s0;
            l8 = l8 * c8 + s8;
#pragma unroll
            for (int dn = 0; dn < 8; dn++) {
                oc[dn][0] *= c0; oc[dn][1] *= c0;
                oc[dn][2] *= c8; oc[dn][3] *= c8;
            }

            __syncwarp();

            // ---- O += P V ----
#pragma unroll
            for (int kc = 0; kc < 8; kc++) {
                unsigned ap[4];
                ap[0] = uP[g * SP_STRIDE + kc * 8 + t4];
                ap[1] = uP[(g + 8) * SP_STRIDE + kc * 8 + t4];
                ap[2] = uP[g * SP_STRIDE + kc * 8 + t4 + 4];
                ap[3] = uP[(g + 8) * SP_STRIDE + kc * 8 + t4 + 4];
#pragma unroll
                for (int dn = 0; dn < 8; dn++) {
                    unsigned b0 = uV[(kc * 8 + t4) * SV_STRIDE + dn * 8 + g];
                    unsigned b1 = uV[(kc * 8 + t4 + 4) * SV_STRIDE + dn * 8 + g];
                    mma1688(oc[dn], ap, b0, b1);
                }
            }
        }
        __syncthreads();
    }

    // ---- epilogue: O / l, merge heads into g_attn [B*S, D] ----
    const float inv0 = 1.f / l0, inv8 = 1.f / l8;
    const int bb = bh >> 4;
    const int h = bh & 15;
    float* D0 = g_attn + ((size_t)(bb * SEQ) + qr0) * DIM + h * HD;
    float* D8 = D0 + 8 * DIM;
#pragma unroll
    for (int dn = 0; dn < 8; dn++) {
        int d = dn * 8 + 2 * t4;
        *reinterpret_cast<float2*>(&D0[d]) =
            make_float2(oc[dn][0] * inv0, oc[dn][1] * inv0);
        *reinterpret_cast<float2*>(&D8[d]) =
            make_float2(oc[dn][2] * inv8, oc[dn][3] * inv8);
    }
}

// ---------------------------------------------------------------------------
extern "C" void kernel_launch(void* const* d_in, const int* in_sizes, int n_in,
                              void* d_out, int out_size)
{
    const float* x      = (const float*)d_in[0];   // [4,1024,1024]
    const float* w_attn = (const float*)d_in[1];   // [1024,3072]
    const float* b_attn = (const float*)d_in[2];   // [3072]
    const float* w_proj = (const float*)d_in[3];   // [1024,1024]
    const float* b_proj = (const float*)d_in[4];   // [1024]
    float* out = (float*)d_out;                    // [4,1024,1024]

    cudaFuncSetAttribute(flash2_kernel,
                         cudaFuncAttributeMaxDynamicSharedMemorySize, FLASH_SMEM);

    // 1) QKV GEMM (TF32) + head-major scatter, q pre-scaled by 0.125*log2e,
    //    q/k/v tf32-rounded for the flash mma stage
    mma_gemm_kernel<0><<<dim3(3 * DIM / 128, MROWS / 128), 256>>>(
        x, w_attn, b_attn, nullptr, 3 * DIM, DIM);

    // 2) tensor-core causal flash attention (writes merged-head g_attn)
    flash2_kernel<<<dim3(SEQ / 128, BSZ * NH), 256, FLASH_SMEM>>>();

    // 3) output projection (TF32 tensor cores)
    mma_gemm_kernel<1><<<dim3(DIM / 128, MROWS / 128), 256>>>(
        nullptr, w_proj, b_proj, out, DIM, DIM);
}